// round 13
// baseline (speedup 1.0000x reference)
#include <cuda_runtime.h>
#include <cstdint>

#define BB 4
#define TT 2048
#define CC 768
#define NROW (BB*TT)                  // 8192
#define NE   (BB*TT*CC)               // 6291456
#define STG_BYTES 32768               // per stage: A(16KB)+B(16KB), BK=32
#define SMEM_DYN (3*STG_BYTES)        // 98304

// ---------------- scratch ----------------
__device__ float g_X  [NE];
__device__ float g_Pi [NE];
__device__ float g_bX [NE];
__device__ float g_bPi[NE];
__device__ float g_Xn [NE];
__device__ float g_XnT[NE];
__device__ float g_E  [(size_t)BB*TT*TT];   // 64 MB
__device__ float g_a  [NROW];
__device__ float g_z  [NROW];
__device__ float g_s  [NROW];
__device__ float g_part[(size_t)NROW*64];

// ---------------- PTX helpers ----------------
__device__ __forceinline__ uint32_t smem_u32(const void* p){
    uint32_t a; asm("{ .reg .u64 t; cvta.to.shared.u64 t, %1; cvt.u32.u64 %0, t; }" : "=r"(a) : "l"(p));
    return a;
}
#define CP16(dst, src) \
    asm volatile("cp.async.cg.shared.global [%0], [%1], 16;" :: "r"(dst), "l"(src) : "memory")
#define CP_COMMIT() asm volatile("cp.async.commit_group;" ::: "memory")
#define CP_WAIT1()  asm volatile("cp.async.wait_group 1;" ::: "memory")

__device__ __forceinline__ uint32_t to_tf32(float f){
    uint32_t r; asm("cvt.rna.tf32.f32 %0, %1;" : "=r"(r) : "f"(f));
    return r;
}
__device__ __forceinline__ void mma_tf32(float* c, const uint32_t* a, const uint32_t* b){
    asm volatile(
        "mma.sync.aligned.m16n8k8.row.col.f32.tf32.tf32.f32 "
        "{%0,%1,%2,%3}, {%4,%5,%6,%7}, {%8,%9}, {%0,%1,%2,%3};"
        : "+f"(c[0]), "+f"(c[1]), "+f"(c[2]), "+f"(c[3])
        : "r"(a[0]), "r"(a[1]), "r"(a[2]), "r"(a[3]), "r"(b[0]), "r"(b[1]));
}
__device__ __forceinline__ void ldsm4(uint32_t* r, uint32_t addr){
    asm volatile("ldmatrix.sync.aligned.m8n8.x4.shared.b16 {%0,%1,%2,%3}, [%4];"
        : "=r"(r[0]), "=r"(r[1]), "=r"(r[2]), "=r"(r[3]) : "r"(addr));
}

__device__ __forceinline__ float blockSum256(float v) {
    __shared__ float red[8];
    int tid = threadIdx.x;
    #pragma unroll
    for (int o = 16; o; o >>= 1) v += __shfl_xor_sync(0xffffffffu, v, o);
    if ((tid & 31) == 0) red[tid >> 5] = v;
    __syncthreads();
    if (tid == 0) {
        float s = 0.f;
        #pragma unroll
        for (int i = 0; i < 8; i++) s += red[i];
        red[0] = s;
    }
    __syncthreads();
    float r = red[0];
    __syncthreads();
    return r;
}
__device__ __forceinline__ float t_of(const int* kp, float toff) {
    return 1.0f + (float)(*kp) + toff;
}

// ---------------- phase-1 LN: fused init (reads Xk,Pk; writes all state) ----------------
__global__ void k_lnsq_init(const float* __restrict__ Xk, const float* __restrict__ Pk,
                            const int* __restrict__ kp, const float* __restrict__ w,
                            float* __restrict__ X, float* __restrict__ Pi,
                            float* __restrict__ bX, float* __restrict__ bPi,
                            float* __restrict__ Xn, float* __restrict__ aout) {
    int row = blockIdx.x, tid = threadIdx.x;
    float t = t_of(kp, 0.0f);
    float Lam = t * t * t;
    const float* x = Xk + (size_t)row * CC;
    const float* pk = Pk + (size_t)row * CC;
    float v[3], pv[3], s = 0.f, sq = 0.f;
    #pragma unroll
    for (int i = 0; i < 3; i++) {
        v[i] = x[tid + 256 * i]; s += v[i];
        pv[i] = Lam * pk[tid + 256 * i]; sq += pv[i] * pv[i];
    }
    s = blockSum256(s);
    float mean = s * (1.0f / CC);
    float q = 0.f;
    #pragma unroll
    for (int i = 0; i < 3; i++) { float d = v[i] - mean; q += d * d; }
    q = blockSum256(q);
    sq = blockSum256(sq);
    if (tid == 0) aout[row] = sq;
    float rstd = rsqrtf(q * (1.0f / CC) + 1e-5f);
    size_t o = (size_t)row * CC;
    #pragma unroll
    for (int i = 0; i < 3; i++) {
        int c = tid + 256 * i;
        X[o + c] = v[i]; bX[o + c] = v[i];
        Pi[o + c] = pv[i]; bPi[o + c] = pv[i];
        Xn[o + c] = __uint_as_float(to_tf32((v[i] - mean) * rstd * w[c]));
    }
}

// ---------------- LayerNorm + fused rowsq of Pin (tf32-rounded out) ----------------
__global__ void k_lnsq(const float* __restrict__ Xin, const float* __restrict__ Pin,
                       const float* __restrict__ w,
                       float* __restrict__ out, float* __restrict__ aout) {
    int row = blockIdx.x, tid = threadIdx.x;
    const float* x = Xin + (size_t)row * CC;
    const float* pp = Pin + (size_t)row * CC;
    float v[3], s = 0.f, sq = 0.f;
    #pragma unroll
    for (int i = 0; i < 3; i++) {
        v[i] = x[tid + 256 * i]; s += v[i];
        float pv = pp[tid + 256 * i]; sq += pv * pv;
    }
    s = blockSum256(s);
    float mean = s * (1.0f / CC);
    float q = 0.f;
    #pragma unroll
    for (int i = 0; i < 3; i++) { float d = v[i] - mean; q += d * d; }
    q = blockSum256(q);
    sq = blockSum256(sq);
    if (tid == 0) aout[row] = sq;
    float rstd = rsqrtf(q * (1.0f / CC) + 1e-5f);
    float* y = out + (size_t)row * CC;
    #pragma unroll
    for (int i = 0; i < 3; i++) {
        int c = tid + 256 * i;
        y[c] = __uint_as_float(to_tf32((v[i] - mean) * rstd * w[c]));
    }
}

// ---------------- LayerNorm (output version, with lam scaling) ----------------
__global__ void k_ln(const float* __restrict__ Xin, const float* __restrict__ w,
                     float* __restrict__ out, const int* __restrict__ kp, float toff) {
    int row = blockIdx.x, tid = threadIdx.x;
    float t = t_of(kp, toff);
    float scale = 1.0f / (t * t * t);
    const float* x = Xin + (size_t)row * CC;
    float v[3], s = 0.f;
    #pragma unroll
    for (int i = 0; i < 3; i++) { v[i] = scale * x[tid + 256 * i]; s += v[i]; }
    s = blockSum256(s);
    float mean = s * (1.0f / CC);
    float q = 0.f;
    #pragma unroll
    for (int i = 0; i < 3; i++) { float d = v[i] - mean; q += d * d; }
    q = blockSum256(q);
    float rstd = rsqrtf(q * (1.0f / CC) + 1e-5f);
    float* y = out + (size_t)row * CC;
    #pragma unroll
    for (int i = 0; i < 3; i++) { int c = tid + 256 * i; y[c] = (v[i] - mean) * rstd * w[c]; }
}

// ---------------- transpose Xn -> XnT [b][C][T] ----------------
__global__ void k_transpose(const float* __restrict__ Xn, float* __restrict__ XnT) {
    __shared__ float tile[32][33];
    int b = blockIdx.z;
    int c0 = blockIdx.x * 32, s0 = blockIdx.y * 32;
    int tx = threadIdx.x, ty = threadIdx.y;
    const float* src = Xn + (size_t)b * TT * CC;
    #pragma unroll
    for (int g = 0; g < 32; g += 8)
        tile[ty + g][tx] = src[(size_t)(s0 + ty + g) * CC + c0 + tx];
    __syncthreads();
    float* dst = XnT + (size_t)b * CC * TT;
    #pragma unroll
    for (int g = 0; g < 32; g += 8)
        dst[(size_t)(c0 + ty + g) * TT + s0 + tx] = tile[tx][ty + g];
}

// ================= gram: mma.sync tf32, BK=32, 3-stage, XOR-swizzled smem =================
__global__ __launch_bounds__(256, 2)
void k_gram_mma(const float* __restrict__ Xn, float* __restrict__ E, float* __restrict__ part) {
    int li = blockIdx.x;
    int bt = (int)((__fsqrt_rn(8.f * li + 1.f) - 1.f) * 0.5f);
    while ((bt + 1) * (bt + 2) / 2 <= li) bt++;
    while (bt * (bt + 1) / 2 > li) bt--;
    int bs = li - bt * (bt + 1) / 2;
    int b = blockIdx.y;

    extern __shared__ char dsm[];
    uint32_t base = smem_u32(dsm);
    int tid = threadIdx.x, wid = tid >> 5, lane = tid & 31;
    int g = lane >> 2, q = lane & 3;
    int warpM = wid & 1, warpN = wid >> 1;
    int t0 = bt << 7, s0 = bs << 7;
    const float* gA = Xn + ((size_t)b * TT + t0) * CC;
    const float* gB = Xn + ((size_t)b * TT + s0) * CC;

    int ldr[4], ldc[4]; uint32_t ldo[4];
    #pragma unroll
    for (int u = 0; u < 4; u++) {
        int idx = tid + u * 256;
        ldr[u] = idx >> 3; ldc[u] = idx & 7;
        ldo[u] = (uint32_t)(ldr[u] * 128 + ((ldc[u] ^ (ldr[u] & 7)) << 4));
    }
    int rowA = lane & 15;
    int rowB = (lane & 7) + ((lane >> 4) << 3);
    uint32_t swA[4], swB[4];
    #pragma unroll
    for (int ks = 0; ks < 4; ks++) {
        swA[ks] = (uint32_t)(((ks * 2 + (lane >> 4)) ^ (lane & 7)) << 4);
        swB[ks] = (uint32_t)(((ks * 2 + ((lane >> 3) & 1)) ^ (lane & 7)) << 4);
    }

    float acc[4][4][4];
    #pragma unroll
    for (int i = 0; i < 4; i++)
        #pragma unroll
        for (int j = 0; j < 4; j++)
            #pragma unroll
            for (int r = 0; r < 4; r++) acc[i][j][r] = 0.f;

    const int NIT = CC / 32;   // 24
    auto issue = [&](int slot, int kk){
        uint32_t so = base + (uint32_t)slot * STG_BYTES;
        #pragma unroll
        for (int u = 0; u < 4; u++) {
            CP16(so + ldo[u],         gA + (size_t)ldr[u] * CC + kk + ldc[u] * 4);
            CP16(so + 16384 + ldo[u], gB + (size_t)ldr[u] * CC + kk + ldc[u] * 4);
        }
    };
    issue(0, 0);  CP_COMMIT();
    issue(1, 32); CP_COMMIT();

    int slot = 0;
    for (int i = 0; i < NIT; i++) {
        CP_WAIT1();
        __syncthreads();
        if (i + 2 < NIT) {
            int ns = slot + 2; if (ns >= 3) ns -= 3;
            issue(ns, (i + 2) * 32);
        }
        CP_COMMIT();
        uint32_t asu = base + (uint32_t)slot * STG_BYTES;
        uint32_t bsu = asu + 16384;
        #pragma unroll
        for (int ks = 0; ks < 4; ks++) {
            uint32_t bf[4][2];
            #pragma unroll
            for (int ntp = 0; ntp < 2; ntp++) {
                uint32_t r4[4];
                ldsm4(r4, bsu + (uint32_t)((warpN * 32 + ntp * 16 + rowB) * 128) + swB[ks]);
                bf[ntp*2][0] = r4[0]; bf[ntp*2][1] = r4[1];
                bf[ntp*2+1][0] = r4[2]; bf[ntp*2+1][1] = r4[3];
            }
            #pragma unroll
            for (int mt = 0; mt < 4; mt++) {
                uint32_t af[4];
                ldsm4(af, asu + (uint32_t)((warpM * 64 + mt * 16 + rowA) * 128) + swA[ks]);
                #pragma unroll
                for (int nt = 0; nt < 4; nt++) mma_tf32(acc[mt][nt], af, bf[nt]);
            }
        }
        slot++; if (slot >= 3) slot = 0;
    }

    bool diag = (bs == bt);
    float* Eb = E + (size_t)b * TT * TT;
    float rowsum[8];
    #pragma unroll
    for (int mt = 0; mt < 4; mt++) {
        #pragma unroll
        for (int rr = 0; rr < 2; rr++) {
            int row = warpM * 64 + mt * 16 + rr * 8 + g;
            int tglob = t0 + row;
            float rs = 0.f;
            #pragma unroll
            for (int nt = 0; nt < 4; nt++) {
                int col = warpN * 32 + nt * 8 + 2 * q;
                float2 v;
                float S0 = fminf(fmaxf(acc[mt][nt][rr*2+0] * (1.0f/96.0f), -60.f), 60.f);
                float S1 = fminf(fmaxf(acc[mt][nt][rr*2+1] * (1.0f/96.0f), -60.f), 60.f);
                v.x = __expf(S0);
                v.y = __expf(S1);
                if (diag) {
                    if (s0 + col     > tglob) v.x = 0.f;
                    if (s0 + col + 1 > tglob) v.y = 0.f;
                }
                rs += v.x + v.y;
                *(float2*)(Eb + (size_t)tglob * TT + s0 + col) = v;
            }
            rowsum[mt * 2 + rr] = rs;
        }
    }
    #pragma unroll
    for (int r = 0; r < 8; r++) {
        float v = rowsum[r];
        v += __shfl_xor_sync(0xffffffffu, v, 1);
        v += __shfl_xor_sync(0xffffffffu, v, 2);
        rowsum[r] = v;
    }
    if (q == 0) {
        #pragma unroll
        for (int mt = 0; mt < 4; mt++)
            #pragma unroll
            for (int rr = 0; rr < 2; rr++) {
                int row = warpM * 64 + mt * 16 + rr * 8 + g;
                part[((size_t)(b * TT + t0 + row)) * 64 + (s0 >> 5) + warpN] = rowsum[mt * 2 + rr];
            }
    }
}

// ---------------- z,s from partials ----------------
__global__ void k_zs2(const float* __restrict__ part, const float* __restrict__ a,
                      const int* __restrict__ kp, float toff,
                      float* __restrict__ z, float* __restrict__ s) {
    int row = blockIdx.x * 256 + threadIdx.x;
    int t = row & (TT - 1);
    int nb = (t >> 5) + 1;
    const float* p = part + (size_t)row * 64;
    float acc = 0.f;
    for (int j = 0; j < nb; j++) acc += p[j];
    float tv = t_of(kp, toff);
    float lam = 1.0f / (tv * tv * tv);
    float zz = fmaxf(acc * (1.0f / TT), 1e-8f);
    z[row] = zz;
    s[row] = (lam * lam * a[row]) / (zz * zz + 1e-8f);
}

// ---------------- escale: E <- tf32(E * (s_t + s_s - 2)) on lower-tri tiles ----------------
__global__ __launch_bounds__(256)
void k_escale(float* __restrict__ E, const float* __restrict__ sv) {
    int li = blockIdx.x;
    int bt = (int)((__fsqrt_rn(8.f * li + 1.f) - 1.f) * 0.5f);
    while ((bt + 1) * (bt + 2) / 2 <= li) bt++;
    while (bt * (bt + 1) / 2 > li) bt--;
    int bs = li - bt * (bt + 1) / 2;
    int b = blockIdx.y;
    int t0 = bt << 7, s0 = bs << 7;
    const float* svb = sv + b * TT;
    __shared__ float scs[128];
    int tid = threadIdx.x;
    if (tid < 128) scs[tid] = svb[s0 + tid] - 2.0f;
    __syncthreads();
    int r = tid >> 1, cb = (tid & 1) << 6;
    float sA = svb[t0 + r];
    float* row = E + ((size_t)b * TT + t0 + r) * TT + s0 + cb;
    #pragma unroll
    for (int j = 0; j < 64; j += 4) {
        float4 v = *(float4*)(row + j);
        float4 sc = *(float4*)&scs[cb + j];
        v.x = __uint_as_float(to_tf32(v.x * (sA + sc.x)));
        v.y = __uint_as_float(to_tf32(v.y * (sA + sc.y)));
        v.z = __uint_as_float(to_tf32(v.z * (sA + sc.z)));
        v.w = __uint_as_float(to_tf32(v.w * (sA + sc.w)));
        *(float4*)(row + j) = v;
    }
}

// ================= force: pure ldsm+mma (E pre-scaled); fused vel + optional rotation =====
__global__ __launch_bounds__(256, 2)
void k_force_mma(const float* __restrict__ E, const float* __restrict__ XnT,
                 const float* __restrict__ zv, const float* __restrict__ Pin,
                 const int* __restrict__ kp, float toff,
                 float* __restrict__ Pupd, float* __restrict__ Xupd,
                 float* __restrict__ XinW, float* __restrict__ PinW,
                 float* __restrict__ outX, int dovel, int dorot) {
    int bc = blockIdx.x;
    int bt = (int)gridDim.y - 1 - (int)blockIdx.y;
    int b = blockIdx.z;
    extern __shared__ char dsm[];
    uint32_t base = smem_u32(dsm);
    int tid = threadIdx.x, wid = tid >> 5, lane = tid & 31;
    int g = lane >> 2, q = lane & 3;
    int warpM = wid & 1, warpN = wid >> 1;
    int t0 = bt << 7, c0 = bc << 7;
    const float* gE = E + ((size_t)b * TT + t0) * TT;
    const float* gB = XnT + ((size_t)b * CC + c0) * TT;

    int ldr[4], ldc[4]; uint32_t ldo[4];
    #pragma unroll
    for (int u = 0; u < 4; u++) {
        int idx = tid + u * 256;
        ldr[u] = idx >> 3; ldc[u] = idx & 7;
        ldo[u] = (uint32_t)(ldr[u] * 128 + ((ldc[u] ^ (ldr[u] & 7)) << 4));
    }
    int rowA = lane & 15;
    int rowB = (lane & 7) + ((lane >> 4) << 3);
    uint32_t swA[4], swB[4];
    #pragma unroll
    for (int ks = 0; ks < 4; ks++) {
        swA[ks] = (uint32_t)(((ks * 2 + (lane >> 4)) ^ (lane & 7)) << 4);
        swB[ks] = (uint32_t)(((ks * 2 + ((lane >> 3) & 1)) ^ (lane & 7)) << 4);
    }

    float acc[4][4][4];
    #pragma unroll
    for (int i = 0; i < 4; i++)
        #pragma unroll
        for (int j = 0; j < 4; j++)
            #pragma unroll
            for (int r = 0; r < 4; r++) acc[i][j][r] = 0.f;

    const int NIT = (bt + 1) * 4;
    auto issue = [&](int slot, int kk){
        uint32_t so = base + (uint32_t)slot * STG_BYTES;
        #pragma unroll
        for (int u = 0; u < 4; u++) {
            CP16(so + ldo[u],         gE + (size_t)ldr[u] * TT + kk + ldc[u] * 4);
            CP16(so + 16384 + ldo[u], gB + (size_t)ldr[u] * TT + kk + ldc[u] * 4);
        }
    };
    issue(0, 0);  CP_COMMIT();
    issue(1, 32); CP_COMMIT();

    int slot = 0;
    for (int i = 0; i < NIT; i++) {
        CP_WAIT1();
        __syncthreads();
        if (i + 2 < NIT) {
            int ns = slot + 2; if (ns >= 3) ns -= 3;
            issue(ns, (i + 2) * 32);
        }
        CP_COMMIT();
        uint32_t asu = base + (uint32_t)slot * STG_BYTES;
        uint32_t bsu = asu + 16384;
        #pragma unroll
        for (int ks = 0; ks < 4; ks++) {
            uint32_t bf[4][2];
            #pragma unroll
            for (int ntp = 0; ntp < 2; ntp++) {
                uint32_t r4[4];
                ldsm4(r4, bsu + (uint32_t)((warpN * 32 + ntp * 16 + rowB) * 128) + swB[ks]);
                bf[ntp*2][0] = r4[0]; bf[ntp*2][1] = r4[1];
                bf[ntp*2+1][0] = r4[2]; bf[ntp*2+1][1] = r4[3];
            }
            #pragma unroll
            for (int mt = 0; mt < 4; mt++) {
                uint32_t af[4];
                ldsm4(af, asu + (uint32_t)((warpM * 64 + mt * 16 + rowA) * 128) + swA[ks]);
                #pragma unroll
                for (int nt = 0; nt < 4; nt++) mma_tf32(acc[mt][nt], af, bf[nt]);
            }
        }
        slot++; if (slot >= 3) slot = 0;
    }

    float tv = t_of(kp, toff);
    float coef = 0.25f * tv * tv * tv / TT;   // tau * Lam / (2T)
    #pragma unroll
    for (int mt = 0; mt < 4; mt++) {
        #pragma unroll
        for (int rr = 0; rr < 2; rr++) {
            int row = warpM * 64 + mt * 16 + rr * 8 + g;
            float* Prow = Pupd + ((size_t)b * TT + t0 + row) * CC + c0;
            #pragma unroll
            for (int nt = 0; nt < 4; nt++) {
                int col = warpN * 32 + nt * 8 + 2 * q;
                float2 v = *(float2*)(Prow + col);
                v.x += coef * acc[mt][nt][rr * 2 + 0];
                v.y += coef * acc[mt][nt][rr * 2 + 1];
                *(float2*)(Prow + col) = v;
            }
        }
    }

    if (dovel) {
        __syncthreads();   // Pupd fragment stores must land before rotation reads them
        float lam = 1.0f / (tv * tv * tv);
        const float* zb = zv + b * TT;
        const float cR  = -0.41614683654714241f;   // cos(2)
        const float snR =  0.90929742682568170f;   // sin(2)
        for (int i4 = tid; i4 < 128 * 32; i4 += 256) {
            int r = i4 >> 5, cc4 = (i4 & 31) << 2;
            size_t gidx = ((size_t)b * TT + t0 + r) * CC + c0 + cc4;
            float w = 0.5f * lam / zb[t0 + r];
            float4 p = *(const float4*)(Pin + gidx);
            float4 x = *(float4*)(Xupd + gidx);
            x.x += w * p.x; x.y += w * p.y; x.z += w * p.z; x.w += w * p.w;
            if (dorot) {
                // canonical (X=Xupd, Pi=Pin, bX=XinW, bPi=Pupd)
                float4 bp = *(const float4*)(Pupd + gidx);
                float4 bx = *(const float4*)(XinW + gidx);
                float xo[4], po[4], bxo[4], bpo[4];
                float* xv = &x.x; float* pv = &p.x; float* bxv = &bx.x; float* bpv = &bp.x;
                #pragma unroll
                for (int e = 0; e < 4; e++) {
                    float dX = xv[e] - bxv[e], dP = pv[e] - bpv[e];
                    float sX = xv[e] + bxv[e], sP = pv[e] + bpv[e];
                    xo[e]  = 0.5f * (sX + cR * dX + snR * dP);
                    po[e]  = 0.5f * (sP - snR * dX + cR * dP);
                    bxo[e] = 0.5f * (sX - cR * dX - snR * dP);
                    bpo[e] = 0.5f * (sP + snR * dX - cR * dP);
                }
                *(float4*)(Xupd + gidx) = make_float4(xo[0], xo[1], xo[2], xo[3]);
                *(float4*)(PinW + gidx) = make_float4(po[0], po[1], po[2], po[3]);
                *(float4*)(XinW + gidx) = make_float4(bxo[0], bxo[1], bxo[2], bxo[3]);
                *(float4*)(Pupd + gidx) = make_float4(bpo[0], bpo[1], bpo[2], bpo[3]);
            } else {
                *(float4*)(Xupd + gidx) = x;
                if (outX) *(float4*)(outX + gidx) = x;
            }
        }
    }
}

// ---------------- launch ----------------
extern "C" void kernel_launch(void* const* d_in, const int* in_sizes, int n_in,
                              void* d_out, int out_size) {
    const float* Xk     = (const float*)d_in[0];
    const float* Pk     = (const float*)d_in[1];
    const float* ln_w   = (const float*)d_in[2];
    const float* ln_v_w = (const float*)d_in[3];
    const int*   kp     = (const int*)  d_in[4];
    float* out = (float*)d_out;

    float *X, *Pi, *bX, *bPi, *Xn, *XnT, *E, *a, *z, *s, *part;
    cudaGetSymbolAddress((void**)&X,   g_X);
    cudaGetSymbolAddress((void**)&Pi,  g_Pi);
    cudaGetSymbolAddress((void**)&bX,  g_bX);
    cudaGetSymbolAddress((void**)&bPi, g_bPi);
    cudaGetSymbolAddress((void**)&Xn,  g_Xn);
    cudaGetSymbolAddress((void**)&XnT, g_XnT);
    cudaGetSymbolAddress((void**)&E,   g_E);
    cudaGetSymbolAddress((void**)&a,   g_a);
    cudaGetSymbolAddress((void**)&z,   g_z);
    cudaGetSymbolAddress((void**)&s,   g_s);
    cudaGetSymbolAddress((void**)&part,g_part);

    static bool attr_done = false;
    if (!attr_done) {
        cudaFuncSetAttribute(k_gram_mma,  cudaFuncAttributeMaxDynamicSharedMemorySize, SMEM_DYN);
        cudaFuncSetAttribute(k_force_mma, cudaFuncAttributeMaxDynamicSharedMemorySize, SMEM_DYN);
        attr_done = true;
    }

    auto mid = [&](const float* Xin, const float* Pin, float toff) {
        k_transpose<<<dim3(24, 64, BB), dim3(32, 8)>>>(Xn, XnT);
        k_gram_mma <<<dim3(136, BB), 256, SMEM_DYN>>>(Xn, E, part);
        k_zs2      <<<NROW / 256, 256>>>(part, a, kp, toff, z, s);
        k_escale   <<<dim3(136, BB), 256>>>(E, s);
    };

    // phase 1 (t = tk): fused init + LN
    k_lnsq_init<<<NROW, 256>>>(Xk, Pk, kp, ln_w, X, Pi, bX, bPi, Xn, a);
    mid(X, bPi, 0.0f);
    k_force_mma<<<dim3(6, 16, BB), 256, SMEM_DYN>>>(E, XnT, z, bPi, kp, 0.0f,
                                                    Pi, bX, nullptr, nullptr, nullptr, 1, 0);
    // phase 2 (t = tk+tau) + fused rotation
    k_lnsq<<<NROW, 256>>>(bX, Pi, ln_w, Xn, a);
    mid(bX, Pi, 0.5f);
    k_force_mma<<<dim3(6, 16, BB), 256, SMEM_DYN>>>(E, XnT, z, Pi, kp, 0.5f,
                                                    bPi, X, bX, Pi, nullptr, 1, 1);
    // phase 3 (t = tk+tau), final X -> out
    k_lnsq<<<NROW, 256>>>(bX, Pi, ln_w, Xn, a);
    mid(bX, Pi, 0.5f);
    k_force_mma<<<dim3(6, 16, BB), 256, SMEM_DYN>>>(E, XnT, z, Pi, kp, 0.5f,
                                                    bPi, X, nullptr, nullptr, out, 1, 0);
    // phase 4 (t = tk+1), Pi kick only
    k_lnsq<<<NROW, 256>>>(X, bPi, ln_w, Xn, a);
    mid(X, bPi, 1.0f);
    k_force_mma<<<dim3(6, 16, BB), 256, SMEM_DYN>>>(E, XnT, z, bPi, kp, 1.0f,
                                                    Pi, bX, nullptr, nullptr, nullptr, 0, 0);

    k_ln<<<NROW, 256>>>(Pi, ln_v_w, out + NE, kp, 1.0f);
}

// round 14
// speedup vs baseline: 1.1882x; 1.1882x over previous
#include <cuda_runtime.h>
#include <cstdint>

#define BB 4
#define TT 2048
#define CC 768
#define NROW (BB*TT)                  // 8192
#define NE   (BB*TT*CC)               // 6291456
#define STG_BYTES 32768               // per stage: A(16KB)+B(16KB), BK=32
#define SMEM_DYN (3*STG_BYTES)        // 98304

// ---------------- scratch ----------------
__device__ float g_X  [NE];
__device__ float g_Pi [NE];
__device__ float g_bX [NE];
__device__ float g_bPi[NE];
__device__ float g_Xn [NE];
__device__ float g_XnT[NE];
__device__ float g_E  [(size_t)BB*TT*TT];   // 64 MB
__device__ float g_a  [NROW];
__device__ float g_z  [NROW];
__device__ float g_s  [NROW];
__device__ float g_part[(size_t)NROW*64];

// ---------------- PTX helpers ----------------
__device__ __forceinline__ uint32_t smem_u32(const void* p){
    uint32_t a; asm("{ .reg .u64 t; cvta.to.shared.u64 t, %1; cvt.u32.u64 %0, t; }" : "=r"(a) : "l"(p));
    return a;
}
#define CP16(dst, src) \
    asm volatile("cp.async.cg.shared.global [%0], [%1], 16;" :: "r"(dst), "l"(src) : "memory")
#define CP_COMMIT() asm volatile("cp.async.commit_group;" ::: "memory")
#define CP_WAIT1()  asm volatile("cp.async.wait_group 1;" ::: "memory")

__device__ __forceinline__ uint32_t to_tf32(float f){
    uint32_t r; asm("cvt.rna.tf32.f32 %0, %1;" : "=r"(r) : "f"(f));
    return r;
}
__device__ __forceinline__ void mma_tf32(float* c, const uint32_t* a, const uint32_t* b){
    asm volatile(
        "mma.sync.aligned.m16n8k8.row.col.f32.tf32.tf32.f32 "
        "{%0,%1,%2,%3}, {%4,%5,%6,%7}, {%8,%9}, {%0,%1,%2,%3};"
        : "+f"(c[0]), "+f"(c[1]), "+f"(c[2]), "+f"(c[3])
        : "r"(a[0]), "r"(a[1]), "r"(a[2]), "r"(a[3]), "r"(b[0]), "r"(b[1]));
}
__device__ __forceinline__ void ldsm4(uint32_t* r, uint32_t addr){
    asm volatile("ldmatrix.sync.aligned.m8n8.x4.shared.b16 {%0,%1,%2,%3}, [%4];"
        : "=r"(r[0]), "=r"(r[1]), "=r"(r[2]), "=r"(r[3]) : "r"(addr));
}

__device__ __forceinline__ float blockSum256(float v) {
    __shared__ float red[8];
    int tid = threadIdx.x;
    #pragma unroll
    for (int o = 16; o; o >>= 1) v += __shfl_xor_sync(0xffffffffu, v, o);
    if ((tid & 31) == 0) red[tid >> 5] = v;
    __syncthreads();
    if (tid == 0) {
        float s = 0.f;
        #pragma unroll
        for (int i = 0; i < 8; i++) s += red[i];
        red[0] = s;
    }
    __syncthreads();
    float r = red[0];
    __syncthreads();
    return r;
}
__device__ __forceinline__ float t_of(const int* kp, float toff) {
    return 1.0f + (float)(*kp) + toff;
}

// ---------------- phase-1 LN: fused init (reads Xk,Pk; writes all state) ----------------
__global__ void k_lnsq_init(const float* __restrict__ Xk, const float* __restrict__ Pk,
                            const int* __restrict__ kp, const float* __restrict__ w,
                            float* __restrict__ X, float* __restrict__ Pi,
                            float* __restrict__ bX, float* __restrict__ bPi,
                            float* __restrict__ Xn, float* __restrict__ aout) {
    int row = blockIdx.x, tid = threadIdx.x;
    float t = t_of(kp, 0.0f);
    float Lam = t * t * t;
    const float* x = Xk + (size_t)row * CC;
    const float* pk = Pk + (size_t)row * CC;
    float v[3], pv[3], s = 0.f, sq = 0.f;
    #pragma unroll
    for (int i = 0; i < 3; i++) {
        v[i] = x[tid + 256 * i]; s += v[i];
        pv[i] = Lam * pk[tid + 256 * i]; sq += pv[i] * pv[i];
    }
    s = blockSum256(s);
    float mean = s * (1.0f / CC);
    float q = 0.f;
    #pragma unroll
    for (int i = 0; i < 3; i++) { float d = v[i] - mean; q += d * d; }
    q = blockSum256(q);
    sq = blockSum256(sq);
    if (tid == 0) aout[row] = sq;
    float rstd = rsqrtf(q * (1.0f / CC) + 1e-5f);
    size_t o = (size_t)row * CC;
    #pragma unroll
    for (int i = 0; i < 3; i++) {
        int c = tid + 256 * i;
        X[o + c] = v[i]; bX[o + c] = v[i];
        Pi[o + c] = pv[i]; bPi[o + c] = pv[i];
        Xn[o + c] = __uint_as_float(to_tf32((v[i] - mean) * rstd * w[c]));
    }
}

// ---------------- LayerNorm + fused rowsq of Pin (tf32-rounded out) ----------------
__global__ void k_lnsq(const float* __restrict__ Xin, const float* __restrict__ Pin,
                       const float* __restrict__ w,
                       float* __restrict__ out, float* __restrict__ aout) {
    int row = blockIdx.x, tid = threadIdx.x;
    const float* x = Xin + (size_t)row * CC;
    const float* pp = Pin + (size_t)row * CC;
    float v[3], s = 0.f, sq = 0.f;
    #pragma unroll
    for (int i = 0; i < 3; i++) {
        v[i] = x[tid + 256 * i]; s += v[i];
        float pv = pp[tid + 256 * i]; sq += pv * pv;
    }
    s = blockSum256(s);
    float mean = s * (1.0f / CC);
    float q = 0.f;
    #pragma unroll
    for (int i = 0; i < 3; i++) { float d = v[i] - mean; q += d * d; }
    q = blockSum256(q);
    sq = blockSum256(sq);
    if (tid == 0) aout[row] = sq;
    float rstd = rsqrtf(q * (1.0f / CC) + 1e-5f);
    float* y = out + (size_t)row * CC;
    #pragma unroll
    for (int i = 0; i < 3; i++) {
        int c = tid + 256 * i;
        y[c] = __uint_as_float(to_tf32((v[i] - mean) * rstd * w[c]));
    }
}

// ---------------- LayerNorm (output version, with lam scaling) ----------------
__global__ void k_ln(const float* __restrict__ Xin, const float* __restrict__ w,
                     float* __restrict__ out, const int* __restrict__ kp, float toff) {
    int row = blockIdx.x, tid = threadIdx.x;
    float t = t_of(kp, toff);
    float scale = 1.0f / (t * t * t);
    const float* x = Xin + (size_t)row * CC;
    float v[3], s = 0.f;
    #pragma unroll
    for (int i = 0; i < 3; i++) { v[i] = scale * x[tid + 256 * i]; s += v[i]; }
    s = blockSum256(s);
    float mean = s * (1.0f / CC);
    float q = 0.f;
    #pragma unroll
    for (int i = 0; i < 3; i++) { float d = v[i] - mean; q += d * d; }
    q = blockSum256(q);
    float rstd = rsqrtf(q * (1.0f / CC) + 1e-5f);
    float* y = out + (size_t)row * CC;
    #pragma unroll
    for (int i = 0; i < 3; i++) { int c = tid + 256 * i; y[c] = (v[i] - mean) * rstd * w[c]; }
}

// ---------------- transpose Xn -> XnT [b][C][T] ----------------
__global__ void k_transpose(const float* __restrict__ Xn, float* __restrict__ XnT) {
    __shared__ float tile[32][33];
    int b = blockIdx.z;
    int c0 = blockIdx.x * 32, s0 = blockIdx.y * 32;
    int tx = threadIdx.x, ty = threadIdx.y;
    const float* src = Xn + (size_t)b * TT * CC;
    #pragma unroll
    for (int g = 0; g < 32; g += 8)
        tile[ty + g][tx] = src[(size_t)(s0 + ty + g) * CC + c0 + tx];
    __syncthreads();
    float* dst = XnT + (size_t)b * CC * TT;
    #pragma unroll
    for (int g = 0; g < 32; g += 8)
        dst[(size_t)(c0 + ty + g) * TT + s0 + tx] = tile[tx][ty + g];
}

// ================= gram: mma.sync tf32, BK=32, 3-stage, XOR-swizzled smem =================
__global__ __launch_bounds__(256, 2)
void k_gram_mma(const float* __restrict__ Xn, float* __restrict__ E, float* __restrict__ part) {
    int li = blockIdx.x;
    int bt = (int)((__fsqrt_rn(8.f * li + 1.f) - 1.f) * 0.5f);
    while ((bt + 1) * (bt + 2) / 2 <= li) bt++;
    while (bt * (bt + 1) / 2 > li) bt--;
    int bs = li - bt * (bt + 1) / 2;
    int b = blockIdx.y;

    extern __shared__ char dsm[];
    uint32_t base = smem_u32(dsm);
    int tid = threadIdx.x, wid = tid >> 5, lane = tid & 31;
    int g = lane >> 2, q = lane & 3;
    int warpM = wid & 1, warpN = wid >> 1;
    int t0 = bt << 7, s0 = bs << 7;
    const float* gA = Xn + ((size_t)b * TT + t0) * CC;
    const float* gB = Xn + ((size_t)b * TT + s0) * CC;

    int ldr[4], ldc[4]; uint32_t ldo[4];
    #pragma unroll
    for (int u = 0; u < 4; u++) {
        int idx = tid + u * 256;
        ldr[u] = idx >> 3; ldc[u] = idx & 7;
        ldo[u] = (uint32_t)(ldr[u] * 128 + ((ldc[u] ^ (ldr[u] & 7)) << 4));
    }
    int rowA = lane & 15;
    int rowB = (lane & 7) + ((lane >> 4) << 3);
    uint32_t swA[4], swB[4];
    #pragma unroll
    for (int ks = 0; ks < 4; ks++) {
        swA[ks] = (uint32_t)(((ks * 2 + (lane >> 4)) ^ (lane & 7)) << 4);
        swB[ks] = (uint32_t)(((ks * 2 + ((lane >> 3) & 1)) ^ (lane & 7)) << 4);
    }

    float acc[4][4][4];
    #pragma unroll
    for (int i = 0; i < 4; i++)
        #pragma unroll
        for (int j = 0; j < 4; j++)
            #pragma unroll
            for (int r = 0; r < 4; r++) acc[i][j][r] = 0.f;

    const int NIT = CC / 32;   // 24
    auto issue = [&](int slot, int kk){
        uint32_t so = base + (uint32_t)slot * STG_BYTES;
        #pragma unroll
        for (int u = 0; u < 4; u++) {
            CP16(so + ldo[u],         gA + (size_t)ldr[u] * CC + kk + ldc[u] * 4);
            CP16(so + 16384 + ldo[u], gB + (size_t)ldr[u] * CC + kk + ldc[u] * 4);
        }
    };
    issue(0, 0);  CP_COMMIT();
    issue(1, 32); CP_COMMIT();

    int slot = 0;
    for (int i = 0; i < NIT; i++) {
        CP_WAIT1();
        __syncthreads();
        if (i + 2 < NIT) {
            int ns = slot + 2; if (ns >= 3) ns -= 3;
            issue(ns, (i + 2) * 32);
        }
        CP_COMMIT();
        uint32_t asu = base + (uint32_t)slot * STG_BYTES;
        uint32_t bsu = asu + 16384;
        #pragma unroll
        for (int ks = 0; ks < 4; ks++) {
            uint32_t bf[4][2];
            #pragma unroll
            for (int ntp = 0; ntp < 2; ntp++) {
                uint32_t r4[4];
                ldsm4(r4, bsu + (uint32_t)((warpN * 32 + ntp * 16 + rowB) * 128) + swB[ks]);
                bf[ntp*2][0] = r4[0]; bf[ntp*2][1] = r4[1];
                bf[ntp*2+1][0] = r4[2]; bf[ntp*2+1][1] = r4[3];
            }
            #pragma unroll
            for (int mt = 0; mt < 4; mt++) {
                uint32_t af[4];
                ldsm4(af, asu + (uint32_t)((warpM * 64 + mt * 16 + rowA) * 128) + swA[ks]);
                #pragma unroll
                for (int nt = 0; nt < 4; nt++) mma_tf32(acc[mt][nt], af, bf[nt]);
            }
        }
        slot++; if (slot >= 3) slot = 0;
    }

    bool diag = (bs == bt);
    float* Eb = E + (size_t)b * TT * TT;
    float rowsum[8];
    #pragma unroll
    for (int mt = 0; mt < 4; mt++) {
        #pragma unroll
        for (int rr = 0; rr < 2; rr++) {
            int row = warpM * 64 + mt * 16 + rr * 8 + g;
            int tglob = t0 + row;
            float rs = 0.f;
            #pragma unroll
            for (int nt = 0; nt < 4; nt++) {
                int col = warpN * 32 + nt * 8 + 2 * q;
                float2 v;
                float S0 = fminf(fmaxf(acc[mt][nt][rr*2+0] * (1.0f/96.0f), -60.f), 60.f);
                float S1 = fminf(fmaxf(acc[mt][nt][rr*2+1] * (1.0f/96.0f), -60.f), 60.f);
                v.x = __expf(S0);
                v.y = __expf(S1);
                if (diag) {
                    if (s0 + col     > tglob) v.x = 0.f;
                    if (s0 + col + 1 > tglob) v.y = 0.f;
                }
                rs += v.x + v.y;
                *(float2*)(Eb + (size_t)tglob * TT + s0 + col) = v;
            }
            rowsum[mt * 2 + rr] = rs;
        }
    }
    #pragma unroll
    for (int r = 0; r < 8; r++) {
        float v = rowsum[r];
        v += __shfl_xor_sync(0xffffffffu, v, 1);
        v += __shfl_xor_sync(0xffffffffu, v, 2);
        rowsum[r] = v;
    }
    if (q == 0) {
        #pragma unroll
        for (int mt = 0; mt < 4; mt++)
            #pragma unroll
            for (int rr = 0; rr < 2; rr++) {
                int row = warpM * 64 + mt * 16 + rr * 8 + g;
                part[((size_t)(b * TT + t0 + row)) * 64 + (s0 >> 5) + warpN] = rowsum[mt * 2 + rr];
            }
    }
}

// ---------------- z,s from partials (warp per row) ----------------
__global__ void k_zs2(const float* __restrict__ part, const float* __restrict__ a,
                      const int* __restrict__ kp, float toff,
                      float* __restrict__ z, float* __restrict__ s) {
    int row = (blockIdx.x * 256 + threadIdx.x) >> 5;
    int lane = threadIdx.x & 31;
    int t = row & (TT - 1);
    int nb = (t >> 5) + 1;
    const float* p = part + (size_t)row * 64;
    float acc = 0.f;
    for (int j = lane; j < nb; j += 32) acc += p[j];
    #pragma unroll
    for (int o = 16; o; o >>= 1) acc += __shfl_xor_sync(0xffffffffu, acc, o);
    if (lane == 0) {
        float tv = t_of(kp, toff);
        float lam = 1.0f / (tv * tv * tv);
        float zz = fmaxf(acc * (1.0f / TT), 1e-8f);
        z[row] = zz;
        s[row] = (lam * lam * a[row]) / (zz * zz + 1e-8f);
    }
}

// ======= force: mma.sync tf32, BK=32, 3-stage, in-loop A-scaling; fused vel + rotation ====
__global__ __launch_bounds__(256, 2)
void k_force_mma(const float* __restrict__ E, const float* __restrict__ XnT,
                 const float* __restrict__ sv, const float* __restrict__ zv,
                 const float* __restrict__ Pin,
                 const int* __restrict__ kp, float toff,
                 float* __restrict__ Pupd, float* __restrict__ Xupd,
                 float* __restrict__ XinW, float* __restrict__ PinW,
                 float* __restrict__ outX, int dovel, int dorot) {
    int bc = blockIdx.x;
    int bt = (int)gridDim.y - 1 - (int)blockIdx.y;   // longest first
    int b = blockIdx.z;
    extern __shared__ char dsm[];
    uint32_t base = smem_u32(dsm);
    int tid = threadIdx.x, wid = tid >> 5, lane = tid & 31;
    int g = lane >> 2, q = lane & 3;
    int warpM = wid & 1, warpN = wid >> 1;
    int t0 = bt << 7, c0 = bc << 7;
    const float* svb = sv + b * TT;
    const float* gE = E + ((size_t)b * TT + t0) * TT;
    const float* gB = XnT + ((size_t)b * CC + c0) * TT;

    int ldr[4], ldc[4]; uint32_t ldo[4];
    #pragma unroll
    for (int u = 0; u < 4; u++) {
        int idx = tid + u * 256;
        ldr[u] = idx >> 3; ldc[u] = idx & 7;
        ldo[u] = (uint32_t)(ldr[u] * 128 + ((ldc[u] ^ (ldr[u] & 7)) << 4));
    }
    int rowA = lane & 15;
    int rowB = (lane & 7) + ((lane >> 4) << 3);
    uint32_t swA[4], swB[4];
    #pragma unroll
    for (int ks = 0; ks < 4; ks++) {
        swA[ks] = (uint32_t)(((ks * 2 + (lane >> 4)) ^ (lane & 7)) << 4);
        swB[ks] = (uint32_t)(((ks * 2 + ((lane >> 3) & 1)) ^ (lane & 7)) << 4);
    }

    float sA2[8];
    #pragma unroll
    for (int mt = 0; mt < 4; mt++) {
        sA2[mt * 2 + 0] = svb[t0 + warpM * 64 + mt * 16 + g]     - 2.0f;
        sA2[mt * 2 + 1] = svb[t0 + warpM * 64 + mt * 16 + 8 + g] - 2.0f;
    }

    float acc[4][4][4];
    #pragma unroll
    for (int i = 0; i < 4; i++)
        #pragma unroll
        for (int j = 0; j < 4; j++)
            #pragma unroll
            for (int r = 0; r < 4; r++) acc[i][j][r] = 0.f;

    const int NIT = (bt + 1) * 4;
    auto issue = [&](int slot, int kk){
        uint32_t so = base + (uint32_t)slot * STG_BYTES;
        #pragma unroll
        for (int u = 0; u < 4; u++) {
            CP16(so + ldo[u],         gE + (size_t)ldr[u] * TT + kk + ldc[u] * 4);
            CP16(so + 16384 + ldo[u], gB + (size_t)ldr[u] * TT + kk + ldc[u] * 4);
        }
    };
    issue(0, 0);  CP_COMMIT();
    issue(1, 32); CP_COMMIT();

    int slot = 0;
    for (int i = 0; i < NIT; i++) {
        CP_WAIT1();
        __syncthreads();
        if (i + 2 < NIT) {
            int ns = slot + 2; if (ns >= 3) ns -= 3;
            issue(ns, (i + 2) * 32);
        }
        CP_COMMIT();
        uint32_t asu = base + (uint32_t)slot * STG_BYTES;
        uint32_t bsu = asu + 16384;
        int kkbase = i * 32;
        #pragma unroll
        for (int ks = 0; ks < 4; ks++) {
            float sc0 = __ldg(&svb[kkbase + ks * 8 + q]);
            float sc1 = __ldg(&svb[kkbase + ks * 8 + 4 + q]);
            uint32_t bf[4][2];
            #pragma unroll
            for (int ntp = 0; ntp < 2; ntp++) {
                uint32_t r4[4];
                ldsm4(r4, bsu + (uint32_t)((warpN * 32 + ntp * 16 + rowB) * 128) + swB[ks]);
                bf[ntp*2][0] = r4[0]; bf[ntp*2][1] = r4[1];
                bf[ntp*2+1][0] = r4[2]; bf[ntp*2+1][1] = r4[3];
            }
            #pragma unroll
            for (int mt = 0; mt < 4; mt++) {
                uint32_t e4[4];
                ldsm4(e4, asu + (uint32_t)((warpM * 64 + mt * 16 + rowA) * 128) + swA[ks]);
                uint32_t af[4];
                af[0] = to_tf32(__uint_as_float(e4[0]) * (sA2[mt*2+0] + sc0));
                af[1] = to_tf32(__uint_as_float(e4[1]) * (sA2[mt*2+1] + sc0));
                af[2] = to_tf32(__uint_as_float(e4[2]) * (sA2[mt*2+0] + sc1));
                af[3] = to_tf32(__uint_as_float(e4[3]) * (sA2[mt*2+1] + sc1));
                #pragma unroll
                for (int nt = 0; nt < 4; nt++) mma_tf32(acc[mt][nt], af, bf[nt]);
            }
        }
        slot++; if (slot >= 3) slot = 0;
    }

    float tv = t_of(kp, toff);
    float coef = 0.25f * tv * tv * tv / TT;   // tau * Lam / (2T)
    #pragma unroll
    for (int mt = 0; mt < 4; mt++) {
        #pragma unroll
        for (int rr = 0; rr < 2; rr++) {
            int row = warpM * 64 + mt * 16 + rr * 8 + g;
            float* Prow = Pupd + ((size_t)b * TT + t0 + row) * CC + c0;
            #pragma unroll
            for (int nt = 0; nt < 4; nt++) {
                int col = warpN * 32 + nt * 8 + 2 * q;
                float2 v = *(float2*)(Prow + col);
                v.x += coef * acc[mt][nt][rr * 2 + 0];
                v.y += coef * acc[mt][nt][rr * 2 + 1];
                *(float2*)(Prow + col) = v;
            }
        }
    }

    if (dovel) {
        float lam = 1.0f / (tv * tv * tv);
        const float* zb = zv + b * TT;
        if (dorot) {
            __syncthreads();   // Pupd fragment stores must land before rotation reads them
            const float cR  = -0.41614683654714241f;   // cos(2)
            const float snR =  0.90929742682568170f;   // sin(2)
            for (int i4 = tid; i4 < 128 * 32; i4 += 256) {
                int r = i4 >> 5, cc4 = (i4 & 31) << 2;
                size_t gidx = ((size_t)b * TT + t0 + r) * CC + c0 + cc4;
                float w = 0.5f * lam / zb[t0 + r];
                float4 p = *(const float4*)(Pin + gidx);
                float4 x = *(float4*)(Xupd + gidx);
                x.x += w * p.x; x.y += w * p.y; x.z += w * p.z; x.w += w * p.w;
                float4 bp = *(const float4*)(Pupd + gidx);
                float4 bx = *(const float4*)(XinW + gidx);
                float* xv = &x.x; float* pv = &p.x; float* bxv = &bx.x; float* bpv = &bp.x;
                float xo[4], po[4], bxo[4], bpo[4];
                #pragma unroll
                for (int e = 0; e < 4; e++) {
                    float dX = xv[e] - bxv[e], dP = pv[e] - bpv[e];
                    float sX = xv[e] + bxv[e], sP = pv[e] + bpv[e];
                    xo[e]  = 0.5f * (sX + cR * dX + snR * dP);
                    po[e]  = 0.5f * (sP - snR * dX + cR * dP);
                    bxo[e] = 0.5f * (sX - cR * dX - snR * dP);
                    bpo[e] = 0.5f * (sP + snR * dX - cR * dP);
                }
                *(float4*)(Xupd + gidx) = make_float4(xo[0], xo[1], xo[2], xo[3]);
                *(float4*)(PinW + gidx) = make_float4(po[0], po[1], po[2], po[3]);
                *(float4*)(XinW + gidx) = make_float4(bxo[0], bxo[1], bxo[2], bxo[3]);
                *(float4*)(Pupd + gidx) = make_float4(bpo[0], bpo[1], bpo[2], bpo[3]);
            }
        } else {
            for (int i4 = tid; i4 < 128 * 32; i4 += 256) {
                int r = i4 >> 5, cc4 = (i4 & 31) << 2;
                size_t gidx = ((size_t)b * TT + t0 + r) * CC + c0 + cc4;
                float w = 0.5f * lam / zb[t0 + r];
                float4 p = *(const float4*)(Pin + gidx);
                float4 x = *(float4*)(Xupd + gidx);
                x.x += w * p.x; x.y += w * p.y; x.z += w * p.z; x.w += w * p.w;
                *(float4*)(Xupd + gidx) = x;
                if (outX) *(float4*)(outX + gidx) = x;
            }
        }
    }
}

// ---------------- launch ----------------
extern "C" void kernel_launch(void* const* d_in, const int* in_sizes, int n_in,
                              void* d_out, int out_size) {
    const float* Xk     = (const float*)d_in[0];
    const float* Pk     = (const float*)d_in[1];
    const float* ln_w   = (const float*)d_in[2];
    const float* ln_v_w = (const float*)d_in[3];
    const int*   kp     = (const int*)  d_in[4];
    float* out = (float*)d_out;

    float *X, *Pi, *bX, *bPi, *Xn, *XnT, *E, *a, *z, *s, *part;
    cudaGetSymbolAddress((void**)&X,   g_X);
    cudaGetSymbolAddress((void**)&Pi,  g_Pi);
    cudaGetSymbolAddress((void**)&bX,  g_bX);
    cudaGetSymbolAddress((void**)&bPi, g_bPi);
    cudaGetSymbolAddress((void**)&Xn,  g_Xn);
    cudaGetSymbolAddress((void**)&XnT, g_XnT);
    cudaGetSymbolAddress((void**)&E,   g_E);
    cudaGetSymbolAddress((void**)&a,   g_a);
    cudaGetSymbolAddress((void**)&z,   g_z);
    cudaGetSymbolAddress((void**)&s,   g_s);
    cudaGetSymbolAddress((void**)&part,g_part);

    static bool attr_done = false;
    if (!attr_done) {
        cudaFuncSetAttribute(k_gram_mma,  cudaFuncAttributeMaxDynamicSharedMemorySize, SMEM_DYN);
        cudaFuncSetAttribute(k_force_mma, cudaFuncAttributeMaxDynamicSharedMemorySize, SMEM_DYN);
        attr_done = true;
    }

    auto mid = [&](float toff) {
        k_transpose<<<dim3(24, 64, BB), dim3(32, 8)>>>(Xn, XnT);
        k_gram_mma <<<dim3(136, BB), 256, SMEM_DYN>>>(Xn, E, part);
        k_zs2      <<<NROW / 8, 256>>>(part, a, kp, toff, z, s);
    };

    // phase 1 (t = tk): fused init + LN
    k_lnsq_init<<<NROW, 256>>>(Xk, Pk, kp, ln_w, X, Pi, bX, bPi, Xn, a);
    mid(0.0f);
    k_force_mma<<<dim3(6, 16, BB), 256, SMEM_DYN>>>(E, XnT, s, z, bPi, kp, 0.0f,
                                                    Pi, bX, nullptr, nullptr, nullptr, 1, 0);
    // phase 2 (t = tk+tau) + fused rotation
    k_lnsq<<<NROW, 256>>>(bX, Pi, ln_w, Xn, a);
    mid(0.5f);
    k_force_mma<<<dim3(6, 16, BB), 256, SMEM_DYN>>>(E, XnT, s, z, Pi, kp, 0.5f,
                                                    bPi, X, bX, Pi, nullptr, 1, 1);
    // phase 3 (t = tk+tau), final X -> out
    k_lnsq<<<NROW, 256>>>(bX, Pi, ln_w, Xn, a);
    mid(0.5f);
    k_force_mma<<<dim3(6, 16, BB), 256, SMEM_DYN>>>(E, XnT, s, z, Pi, kp, 0.5f,
                                                    bPi, X, nullptr, nullptr, out, 1, 0);
    // phase 4 (t = tk+1), Pi kick only
    k_lnsq<<<NROW, 256>>>(X, bPi, ln_w, Xn, a);
    mid(1.0f);
    k_force_mma<<<dim3(6, 16, BB), 256, SMEM_DYN>>>(E, XnT, s, z, bPi, kp, 1.0f,
                                                    Pi, bX, nullptr, nullptr, nullptr, 0, 0);

    k_ln<<<NROW, 256>>>(Pi, ln_v_w, out + NE, kp, 1.0f);
}

// round 15
// speedup vs baseline: 1.2708x; 1.0696x over previous
#include <cuda_runtime.h>
#include <cstdint>

#define BB 4
#define TT 2048
#define CC 768
#define NROW (BB*TT)                  // 8192
#define NE   (BB*TT*CC)               // 6291456
#define STG_BYTES 32768               // per stage: A(16KB)+B(16KB), BK=32
#define SMEM_DYN (3*STG_BYTES)        // 98304

// ---------------- scratch ----------------
__device__ float g_X  [NE];
__device__ float g_Pi [NE];
__device__ float g_bX [NE];
__device__ float g_bPi[NE];
__device__ float g_Xn [NE];
__device__ float g_XnT[NE];
__device__ float g_E  [(size_t)BB*TT*TT];   // 64 MB
__device__ float g_a  [NROW];
__device__ float g_z  [NROW];
__device__ float g_s  [NROW];
__device__ float g_part[(size_t)NROW*64];

// ---------------- PTX helpers ----------------
__device__ __forceinline__ uint32_t smem_u32(const void* p){
    uint32_t a; asm("{ .reg .u64 t; cvta.to.shared.u64 t, %1; cvt.u32.u64 %0, t; }" : "=r"(a) : "l"(p));
    return a;
}
#define CP16(dst, src) \
    asm volatile("cp.async.cg.shared.global [%0], [%1], 16;" :: "r"(dst), "l"(src) : "memory")
#define CP_COMMIT() asm volatile("cp.async.commit_group;" ::: "memory")
#define CP_WAIT1()  asm volatile("cp.async.wait_group 1;" ::: "memory")

__device__ __forceinline__ uint32_t to_tf32(float f){
    uint32_t r; asm("cvt.rna.tf32.f32 %0, %1;" : "=r"(r) : "f"(f));
    return r;
}
__device__ __forceinline__ void mma_tf32(float* c, const uint32_t* a, const uint32_t* b){
    asm volatile(
        "mma.sync.aligned.m16n8k8.row.col.f32.tf32.tf32.f32 "
        "{%0,%1,%2,%3}, {%4,%5,%6,%7}, {%8,%9}, {%0,%1,%2,%3};"
        : "+f"(c[0]), "+f"(c[1]), "+f"(c[2]), "+f"(c[3])
        : "r"(a[0]), "r"(a[1]), "r"(a[2]), "r"(a[3]), "r"(b[0]), "r"(b[1]));
}
__device__ __forceinline__ void ldsm4(uint32_t* r, uint32_t addr){
    asm volatile("ldmatrix.sync.aligned.m8n8.x4.shared.b16 {%0,%1,%2,%3}, [%4];"
        : "=r"(r[0]), "=r"(r[1]), "=r"(r[2]), "=r"(r[3]) : "r"(addr));
}
__device__ __forceinline__ float warpSum(float v){
    #pragma unroll
    for (int o = 16; o; o >>= 1) v += __shfl_xor_sync(0xffffffffu, v, o);
    return v;
}
__device__ __forceinline__ float t_of(const int* kp, float toff) {
    return 1.0f + (float)(*kp) + toff;
}

// ---------------- phase-1 LN: fused init, warp-per-row ----------------
__global__ void k_lnsq_init(const float* __restrict__ Xk, const float* __restrict__ Pk,
                            const int* __restrict__ kp, const float* __restrict__ w,
                            float* __restrict__ X, float* __restrict__ Pi,
                            float* __restrict__ bX, float* __restrict__ bPi,
                            float* __restrict__ Xn, float* __restrict__ aout) {
    int row = blockIdx.x * 8 + (threadIdx.x >> 5);
    int lane = threadIdx.x & 31;
    float t = t_of(kp, 0.0f);
    float Lam = t * t * t;
    const float* x = Xk + (size_t)row * CC;
    const float* pk = Pk + (size_t)row * CC;
    float v[24], pv[24], s = 0.f, sq = 0.f;
    #pragma unroll
    for (int j = 0; j < 24; j++) {
        v[j] = x[lane + 32 * j]; s += v[j];
        pv[j] = Lam * pk[lane + 32 * j]; sq += pv[j] * pv[j];
    }
    s = warpSum(s); sq = warpSum(sq);
    float mean = s * (1.0f / CC);
    float q = 0.f;
    #pragma unroll
    for (int j = 0; j < 24; j++) { float d = v[j] - mean; q += d * d; }
    q = warpSum(q);
    if (lane == 0) aout[row] = sq;
    float rstd = rsqrtf(q * (1.0f / CC) + 1e-5f);
    size_t o = (size_t)row * CC;
    #pragma unroll
    for (int j = 0; j < 24; j++) {
        int c = lane + 32 * j;
        X[o + c] = v[j]; bX[o + c] = v[j];
        Pi[o + c] = pv[j]; bPi[o + c] = pv[j];
        Xn[o + c] = __uint_as_float(to_tf32((v[j] - mean) * rstd * w[c]));
    }
}

// ---------------- LN + fused rowsq, warp-per-row ----------------
__global__ void k_lnsq(const float* __restrict__ Xin, const float* __restrict__ Pin,
                       const float* __restrict__ w,
                       float* __restrict__ out, float* __restrict__ aout) {
    int row = blockIdx.x * 8 + (threadIdx.x >> 5);
    int lane = threadIdx.x & 31;
    const float* x = Xin + (size_t)row * CC;
    const float* pp = Pin + (size_t)row * CC;
    float v[24], s = 0.f, sq = 0.f;
    #pragma unroll
    for (int j = 0; j < 24; j++) {
        v[j] = x[lane + 32 * j]; s += v[j];
        float p = pp[lane + 32 * j]; sq += p * p;
    }
    s = warpSum(s); sq = warpSum(sq);
    float mean = s * (1.0f / CC);
    float q = 0.f;
    #pragma unroll
    for (int j = 0; j < 24; j++) { float d = v[j] - mean; q += d * d; }
    q = warpSum(q);
    if (lane == 0) aout[row] = sq;
    float rstd = rsqrtf(q * (1.0f / CC) + 1e-5f);
    float* y = out + (size_t)row * CC;
    #pragma unroll
    for (int j = 0; j < 24; j++) {
        int c = lane + 32 * j;
        y[c] = __uint_as_float(to_tf32((v[j] - mean) * rstd * w[c]));
    }
}

// ---------------- final LN (with lam scaling), warp-per-row ----------------
__global__ void k_ln(const float* __restrict__ Xin, const float* __restrict__ w,
                     float* __restrict__ out, const int* __restrict__ kp, float toff) {
    int row = blockIdx.x * 8 + (threadIdx.x >> 5);
    int lane = threadIdx.x & 31;
    float t = t_of(kp, toff);
    float scale = 1.0f / (t * t * t);
    const float* x = Xin + (size_t)row * CC;
    float v[24], s = 0.f;
    #pragma unroll
    for (int j = 0; j < 24; j++) { v[j] = scale * x[lane + 32 * j]; s += v[j]; }
    s = warpSum(s);
    float mean = s * (1.0f / CC);
    float q = 0.f;
    #pragma unroll
    for (int j = 0; j < 24; j++) { float d = v[j] - mean; q += d * d; }
    q = warpSum(q);
    float rstd = rsqrtf(q * (1.0f / CC) + 1e-5f);
    float* y = out + (size_t)row * CC;
    #pragma unroll
    for (int j = 0; j < 24; j++) { int c = lane + 32 * j; y[c] = (v[j] - mean) * rstd * w[c]; }
}

// ---------------- transpose Xn -> XnT [b][C][T] ----------------
__global__ void k_transpose(const float* __restrict__ Xn, float* __restrict__ XnT) {
    __shared__ float tile[32][33];
    int b = blockIdx.z;
    int c0 = blockIdx.x * 32, s0 = blockIdx.y * 32;
    int tx = threadIdx.x, ty = threadIdx.y;
    const float* src = Xn + (size_t)b * TT * CC;
    #pragma unroll
    for (int g = 0; g < 32; g += 8)
        tile[ty + g][tx] = src[(size_t)(s0 + ty + g) * CC + c0 + tx];
    __syncthreads();
    float* dst = XnT + (size_t)b * CC * TT;
    #pragma unroll
    for (int g = 0; g < 32; g += 8)
        dst[(size_t)(c0 + ty + g) * TT + s0 + tx] = tile[tx][ty + g];
}

// ================= gram: mma.sync tf32, BK=32, 3-stage, XOR-swizzled smem =================
__global__ __launch_bounds__(256, 2)
void k_gram_mma(const float* __restrict__ Xn, float* __restrict__ E, float* __restrict__ part) {
    int li = blockIdx.x;
    int bt = (int)((__fsqrt_rn(8.f * li + 1.f) - 1.f) * 0.5f);
    while ((bt + 1) * (bt + 2) / 2 <= li) bt++;
    while (bt * (bt + 1) / 2 > li) bt--;
    int bs = li - bt * (bt + 1) / 2;
    int b = blockIdx.y;

    extern __shared__ char dsm[];
    uint32_t base = smem_u32(dsm);
    int tid = threadIdx.x, wid = tid >> 5, lane = tid & 31;
    int g = lane >> 2, q = lane & 3;
    int warpM = wid & 1, warpN = wid >> 1;
    int t0 = bt << 7, s0 = bs << 7;
    bool diag = (bs == bt);
    bool skipw = diag && (warpM == 0) && (warpN >= 2);   // fully-masked warp tile
    const float* gA = Xn + ((size_t)b * TT + t0) * CC;
    const float* gB = Xn + ((size_t)b * TT + s0) * CC;

    int ldr[4], ldc[4]; uint32_t ldo[4];
    #pragma unroll
    for (int u = 0; u < 4; u++) {
        int idx = tid + u * 256;
        ldr[u] = idx >> 3; ldc[u] = idx & 7;
        ldo[u] = (uint32_t)(ldr[u] * 128 + ((ldc[u] ^ (ldr[u] & 7)) << 4));
    }
    int rowA = lane & 15;
    int rowB = (lane & 7) + ((lane >> 4) << 3);
    uint32_t swA[4], swB[4];
    #pragma unroll
    for (int ks = 0; ks < 4; ks++) {
        swA[ks] = (uint32_t)(((ks * 2 + (lane >> 4)) ^ (lane & 7)) << 4);
        swB[ks] = (uint32_t)(((ks * 2 + ((lane >> 3) & 1)) ^ (lane & 7)) << 4);
    }

    float acc[4][4][4];
    #pragma unroll
    for (int i = 0; i < 4; i++)
        #pragma unroll
        for (int j = 0; j < 4; j++)
            #pragma unroll
            for (int r = 0; r < 4; r++) acc[i][j][r] = 0.f;

    const int NIT = CC / 32;   // 24
    auto issue = [&](int slot, int kk){
        uint32_t so = base + (uint32_t)slot * STG_BYTES;
        #pragma unroll
        for (int u = 0; u < 4; u++) {
            CP16(so + ldo[u],         gA + (size_t)ldr[u] * CC + kk + ldc[u] * 4);
            CP16(so + 16384 + ldo[u], gB + (size_t)ldr[u] * CC + kk + ldc[u] * 4);
        }
    };
    issue(0, 0);  CP_COMMIT();
    issue(1, 32); CP_COMMIT();

    int slot = 0;
    for (int i = 0; i < NIT; i++) {
        CP_WAIT1();
        __syncthreads();
        if (i + 2 < NIT) {
            int ns = slot + 2; if (ns >= 3) ns -= 3;
            issue(ns, (i + 2) * 32);
        }
        CP_COMMIT();
        if (!skipw) {
            uint32_t asu = base + (uint32_t)slot * STG_BYTES;
            uint32_t bsu = asu + 16384;
            #pragma unroll
            for (int ks = 0; ks < 4; ks++) {
                uint32_t bf[4][2];
                #pragma unroll
                for (int ntp = 0; ntp < 2; ntp++) {
                    uint32_t r4[4];
                    ldsm4(r4, bsu + (uint32_t)((warpN * 32 + ntp * 16 + rowB) * 128) + swB[ks]);
                    bf[ntp*2][0] = r4[0]; bf[ntp*2][1] = r4[1];
                    bf[ntp*2+1][0] = r4[2]; bf[ntp*2+1][1] = r4[3];
                }
                #pragma unroll
                for (int mt = 0; mt < 4; mt++) {
                    uint32_t af[4];
                    ldsm4(af, asu + (uint32_t)((warpM * 64 + mt * 16 + rowA) * 128) + swA[ks]);
                    #pragma unroll
                    for (int nt = 0; nt < 4; nt++) mma_tf32(acc[mt][nt], af, bf[nt]);
                }
            }
        }
        slot++; if (slot >= 3) slot = 0;
    }

    float* Eb = E + (size_t)b * TT * TT;
    float rowsum[8];
    #pragma unroll
    for (int mt = 0; mt < 4; mt++) {
        #pragma unroll
        for (int rr = 0; rr < 2; rr++) {
            int row = warpM * 64 + mt * 16 + rr * 8 + g;
            int tglob = t0 + row;
            float rs = 0.f;
            #pragma unroll
            for (int nt = 0; nt < 4; nt++) {
                int col = warpN * 32 + nt * 8 + 2 * q;
                float2 v;
                float S0 = fminf(fmaxf(acc[mt][nt][rr*2+0] * (1.0f/96.0f), -60.f), 60.f);
                float S1 = fminf(fmaxf(acc[mt][nt][rr*2+1] * (1.0f/96.0f), -60.f), 60.f);
                v.x = __expf(S0);
                v.y = __expf(S1);
                if (diag) {
                    if (s0 + col     > tglob) v.x = 0.f;
                    if (s0 + col + 1 > tglob) v.y = 0.f;
                }
                rs += v.x + v.y;
                *(float2*)(Eb + (size_t)tglob * TT + s0 + col) = v;
            }
            rowsum[mt * 2 + rr] = rs;
        }
    }
    #pragma unroll
    for (int r = 0; r < 8; r++) {
        float v = rowsum[r];
        v += __shfl_xor_sync(0xffffffffu, v, 1);
        v += __shfl_xor_sync(0xffffffffu, v, 2);
        rowsum[r] = v;
    }
    if (q == 0) {
        #pragma unroll
        for (int mt = 0; mt < 4; mt++)
            #pragma unroll
            for (int rr = 0; rr < 2; rr++) {
                int row = warpM * 64 + mt * 16 + rr * 8 + g;
                part[((size_t)(b * TT + t0 + row)) * 64 + (s0 >> 5) + warpN] = rowsum[mt * 2 + rr];
            }
    }
}

// ---------------- z,s from partials (warp per row) ----------------
__global__ void k_zs2(const float* __restrict__ part, const float* __restrict__ a,
                      const int* __restrict__ kp, float toff,
                      float* __restrict__ z, float* __restrict__ s) {
    int row = (blockIdx.x * 256 + threadIdx.x) >> 5;
    int lane = threadIdx.x & 31;
    int t = row & (TT - 1);
    int nb = (t >> 5) + 1;
    const float* p = part + (size_t)row * 64;
    float acc = 0.f;
    for (int j = lane; j < nb; j += 32) acc += p[j];
    acc = warpSum(acc);
    if (lane == 0) {
        float tv = t_of(kp, toff);
        float lam = 1.0f / (tv * tv * tv);
        float zz = fmaxf(acc * (1.0f / TT), 1e-8f);
        z[row] = zz;
        s[row] = (lam * lam * a[row]) / (zz * zz + 1e-8f);
    }
}

// ======= force: 4Mx2N warp tile (halved A-scale ALU); fused vel + rotation =====
__global__ __launch_bounds__(256, 2)
void k_force_mma(const float* __restrict__ E, const float* __restrict__ XnT,
                 const float* __restrict__ sv, const float* __restrict__ zv,
                 const float* __restrict__ Pin,
                 const int* __restrict__ kp, float toff,
                 float* __restrict__ Pupd, float* __restrict__ Xupd,
                 float* __restrict__ XinW, float* __restrict__ PinW,
                 float* __restrict__ outX, int dovel, int dorot) {
    int bc = blockIdx.x;
    int bt = (int)gridDim.y - 1 - (int)blockIdx.y;   // longest first
    int b = blockIdx.z;
    extern __shared__ char dsm[];
    uint32_t base = smem_u32(dsm);
    int tid = threadIdx.x, wid = tid >> 5, lane = tid & 31;
    int g = lane >> 2, q = lane & 3;
    int warpM = wid >> 1, warpN = wid & 1;   // 4M x 2N: warp tile 32 x 64
    int t0 = bt << 7, c0 = bc << 7;
    const float* svb = sv + b * TT;
    const float* gE = E + ((size_t)b * TT + t0) * TT;
    const float* gB = XnT + ((size_t)b * CC + c0) * TT;

    int ldr[4], ldc[4]; uint32_t ldo[4];
    #pragma unroll
    for (int u = 0; u < 4; u++) {
        int idx = tid + u * 256;
        ldr[u] = idx >> 3; ldc[u] = idx & 7;
        ldo[u] = (uint32_t)(ldr[u] * 128 + ((ldc[u] ^ (ldr[u] & 7)) << 4));
    }
    int rowA = lane & 15;
    int rowB = (lane & 7) + ((lane >> 4) << 3);
    uint32_t swA[4], swB[4];
    #pragma unroll
    for (int ks = 0; ks < 4; ks++) {
        swA[ks] = (uint32_t)(((ks * 2 + (lane >> 4)) ^ (lane & 7)) << 4);
        swB[ks] = (uint32_t)(((ks * 2 + ((lane >> 3) & 1)) ^ (lane & 7)) << 4);
    }

    float sA2[4];
    #pragma unroll
    for (int mt = 0; mt < 2; mt++) {
        sA2[mt * 2 + 0] = svb[t0 + warpM * 32 + mt * 16 + g]     - 2.0f;
        sA2[mt * 2 + 1] = svb[t0 + warpM * 32 + mt * 16 + 8 + g] - 2.0f;
    }

    float acc[2][8][4];
    #pragma unroll
    for (int i = 0; i < 2; i++)
        #pragma unroll
        for (int j = 0; j < 8; j++)
            #pragma unroll
            for (int r = 0; r < 4; r++) acc[i][j][r] = 0.f;

    const int NIT = (bt + 1) * 4;
    auto issue = [&](int slot, int kk){
        uint32_t so = base + (uint32_t)slot * STG_BYTES;
        #pragma unroll
        for (int u = 0; u < 4; u++) {
            CP16(so + ldo[u],         gE + (size_t)ldr[u] * TT + kk + ldc[u] * 4);
            CP16(so + 16384 + ldo[u], gB + (size_t)ldr[u] * TT + kk + ldc[u] * 4);
        }
    };
    issue(0, 0);  CP_COMMIT();
    issue(1, 32); CP_COMMIT();

    int slot = 0;
    for (int i = 0; i < NIT; i++) {
        CP_WAIT1();
        __syncthreads();
        if (i + 2 < NIT) {
            int ns = slot + 2; if (ns >= 3) ns -= 3;
            issue(ns, (i + 2) * 32);
        }
        CP_COMMIT();
        uint32_t asu = base + (uint32_t)slot * STG_BYTES;
        uint32_t bsu = asu + 16384;
        int kkbase = i * 32;
        #pragma unroll
        for (int ks = 0; ks < 4; ks++) {
            float sc0 = __ldg(&svb[kkbase + ks * 8 + q]);
            float sc1 = __ldg(&svb[kkbase + ks * 8 + 4 + q]);
            uint32_t bf[8][2];
            #pragma unroll
            for (int ntp = 0; ntp < 4; ntp++) {
                uint32_t r4[4];
                ldsm4(r4, bsu + (uint32_t)((warpN * 64 + ntp * 16 + rowB) * 128) + swB[ks]);
                bf[ntp*2][0] = r4[0]; bf[ntp*2][1] = r4[1];
                bf[ntp*2+1][0] = r4[2]; bf[ntp*2+1][1] = r4[3];
            }
            #pragma unroll
            for (int mt = 0; mt < 2; mt++) {
                uint32_t e4[4];
                ldsm4(e4, asu + (uint32_t)((warpM * 32 + mt * 16 + rowA) * 128) + swA[ks]);
                uint32_t af[4];
                af[0] = to_tf32(__uint_as_float(e4[0]) * (sA2[mt*2+0] + sc0));
                af[1] = to_tf32(__uint_as_float(e4[1]) * (sA2[mt*2+1] + sc0));
                af[2] = to_tf32(__uint_as_float(e4[2]) * (sA2[mt*2+0] + sc1));
                af[3] = to_tf32(__uint_as_float(e4[3]) * (sA2[mt*2+1] + sc1));
                #pragma unroll
                for (int nt = 0; nt < 8; nt++) mma_tf32(acc[mt][nt], af, bf[nt]);
            }
        }
        slot++; if (slot >= 3) slot = 0;
    }

    float tv = t_of(kp, toff);
    float coef = 0.25f * tv * tv * tv / TT;   // tau * Lam / (2T)
    #pragma unroll
    for (int mt = 0; mt < 2; mt++) {
        #pragma unroll
        for (int rr = 0; rr < 2; rr++) {
            int row = warpM * 32 + mt * 16 + rr * 8 + g;
            float* Prow = Pupd + ((size_t)b * TT + t0 + row) * CC + c0;
            #pragma unroll
            for (int nt = 0; nt < 8; nt++) {
                int col = warpN * 64 + nt * 8 + 2 * q;
                float2 v = *(float2*)(Prow + col);
                v.x += coef * acc[mt][nt][rr * 2 + 0];
                v.y += coef * acc[mt][nt][rr * 2 + 1];
                *(float2*)(Prow + col) = v;
            }
        }
    }

    if (dovel) {
        float lam = 1.0f / (tv * tv * tv);
        const float* zb = zv + b * TT;
        if (dorot) {
            __syncthreads();   // Pupd fragment stores must land before rotation reads them
            const float cR  = -0.41614683654714241f;   // cos(2)
            const float snR =  0.90929742682568170f;   // sin(2)
            for (int i4 = tid; i4 < 128 * 32; i4 += 256) {
                int r = i4 >> 5, cc4 = (i4 & 31) << 2;
                size_t gidx = ((size_t)b * TT + t0 + r) * CC + c0 + cc4;
                float w = 0.5f * lam / zb[t0 + r];
                float4 p = *(const float4*)(Pin + gidx);
                float4 x = *(float4*)(Xupd + gidx);
                x.x += w * p.x; x.y += w * p.y; x.z += w * p.z; x.w += w * p.w;
                float4 bp = *(const float4*)(Pupd + gidx);
                float4 bx = *(const float4*)(XinW + gidx);
                float* xv = &x.x; float* pv = &p.x; float* bxv = &bx.x; float* bpv = &bp.x;
                float xo[4], po[4], bxo[4], bpo[4];
                #pragma unroll
                for (int e = 0; e < 4; e++) {
                    float dX = xv[e] - bxv[e], dP = pv[e] - bpv[e];
                    float sX = xv[e] + bxv[e], sP = pv[e] + bpv[e];
                    xo[e]  = 0.5f * (sX + cR * dX + snR * dP);
                    po[e]  = 0.5f * (sP - snR * dX + cR * dP);
                    bxo[e] = 0.5f * (sX - cR * dX - snR * dP);
                    bpo[e] = 0.5f * (sP + snR * dX - cR * dP);
                }
                *(float4*)(Xupd + gidx) = make_float4(xo[0], xo[1], xo[2], xo[3]);
                *(float4*)(PinW + gidx) = make_float4(po[0], po[1], po[2], po[3]);
                *(float4*)(XinW + gidx) = make_float4(bxo[0], bxo[1], bxo[2], bxo[3]);
                *(float4*)(Pupd + gidx) = make_float4(bpo[0], bpo[1], bpo[2], bpo[3]);
            }
        } else {
            for (int i4 = tid; i4 < 128 * 32; i4 += 256) {
                int r = i4 >> 5, cc4 = (i4 & 31) << 2;
                size_t gidx = ((size_t)b * TT + t0 + r) * CC + c0 + cc4;
                float w = 0.5f * lam / zb[t0 + r];
                float4 p = *(const float4*)(Pin + gidx);
                float4 x = *(float4*)(Xupd + gidx);
                x.x += w * p.x; x.y += w * p.y; x.z += w * p.z; x.w += w * p.w;
                *(float4*)(Xupd + gidx) = x;
                if (outX) *(float4*)(outX + gidx) = x;
            }
        }
    }
}

// ---------------- launch ----------------
extern "C" void kernel_launch(void* const* d_in, const int* in_sizes, int n_in,
                              void* d_out, int out_size) {
    const float* Xk     = (const float*)d_in[0];
    const float* Pk     = (const float*)d_in[1];
    const float* ln_w   = (const float*)d_in[2];
    const float* ln_v_w = (const float*)d_in[3];
    const int*   kp     = (const int*)  d_in[4];
    float* out = (float*)d_out;

    float *X, *Pi, *bX, *bPi, *Xn, *XnT, *E, *a, *z, *s, *part;
    cudaGetSymbolAddress((void**)&X,   g_X);
    cudaGetSymbolAddress((void**)&Pi,  g_Pi);
    cudaGetSymbolAddress((void**)&bX,  g_bX);
    cudaGetSymbolAddress((void**)&bPi, g_bPi);
    cudaGetSymbolAddress((void**)&Xn,  g_Xn);
    cudaGetSymbolAddress((void**)&XnT, g_XnT);
    cudaGetSymbolAddress((void**)&E,   g_E);
    cudaGetSymbolAddress((void**)&a,   g_a);
    cudaGetSymbolAddress((void**)&z,   g_z);
    cudaGetSymbolAddress((void**)&s,   g_s);
    cudaGetSymbolAddress((void**)&part,g_part);

    static bool attr_done = false;
    if (!attr_done) {
        cudaFuncSetAttribute(k_gram_mma,  cudaFuncAttributeMaxDynamicSharedMemorySize, SMEM_DYN);
        cudaFuncSetAttribute(k_force_mma, cudaFuncAttributeMaxDynamicSharedMemorySize, SMEM_DYN);
        attr_done = true;
    }

    auto mid = [&](float toff) {
        k_transpose<<<dim3(24, 64, BB), dim3(32, 8)>>>(Xn, XnT);
        k_gram_mma <<<dim3(136, BB), 256, SMEM_DYN>>>(Xn, E, part);
        k_zs2      <<<NROW / 8, 256>>>(part, a, kp, toff, z, s);
    };

    // phase 1 (t = tk): fused init + LN
    k_lnsq_init<<<NROW / 8, 256>>>(Xk, Pk, kp, ln_w, X, Pi, bX, bPi, Xn, a);
    mid(0.0f);
    k_force_mma<<<dim3(6, 16, BB), 256, SMEM_DYN>>>(E, XnT, s, z, bPi, kp, 0.0f,
                                                    Pi, bX, nullptr, nullptr, nullptr, 1, 0);
    // phase 2 (t = tk+tau) + fused rotation
    k_lnsq<<<NROW / 8, 256>>>(bX, Pi, ln_w, Xn, a);
    mid(0.5f);
    k_force_mma<<<dim3(6, 16, BB), 256, SMEM_DYN>>>(E, XnT, s, z, Pi, kp, 0.5f,
                                                    bPi, X, bX, Pi, nullptr, 1, 1);
    // phase 3 (t = tk+tau), final X -> out
    k_lnsq<<<NROW / 8, 256>>>(bX, Pi, ln_w, Xn, a);
    mid(0.5f);
    k_force_mma<<<dim3(6, 16, BB), 256, SMEM_DYN>>>(E, XnT, s, z, Pi, kp, 0.5f,
                                                    bPi, X, nullptr, nullptr, out, 1, 0);
    // phase 4 (t = tk+1), Pi kick only
    k_lnsq<<<NROW / 8, 256>>>(X, bPi, ln_w, Xn, a);
    mid(1.0f);
    k_force_mma<<<dim3(6, 16, BB), 256, SMEM_DYN>>>(E, XnT, s, z, bPi, kp, 1.0f,
                                                    Pi, bX, nullptr, nullptr, nullptr, 0, 0);

    k_ln<<<NROW / 8, 256>>>(Pi, ln_v_w, out + NE, kp, 1.0f);
}